// round 9
// baseline (speedup 1.0000x reference)
#include <cuda_runtime.h>
#include <cstdint>

#define T_STEPS 2048
#define BATCH   32
#define INDIM   512
#define HID     512
#define G4      2048   // 4*HID

typedef unsigned long long u64;

__device__ __forceinline__ u64 pk2(float x) {
    u64 r; asm("mov.b64 %0, {%1, %1};" : "=l"(r) : "f"(x)); return r;
}
__device__ __forceinline__ void ffma2(u64& d, u64 a, u64 b, u64 c) {
    asm("fma.rn.f32x2 %0, %1, %2, %3;" : "=l"(d) : "l"(a), "l"(b), "l"(c));
}
__device__ __forceinline__ void fadd2(u64& d, u64 a, u64 b) {
    asm("add.rn.f32x2 %0, %1, %2;" : "=l"(d) : "l"(a), "l"(b));
}
__device__ __forceinline__ float2 up2(u64 v) {
    float2 f; asm("mov.b64 {%0, %1}, %2;" : "=f"(f.x), "=f"(f.y) : "l"(v)); return f;
}
__device__ __forceinline__ float tanhfast(float x) {
    float r; asm("tanh.approx.f32 %0, %1;" : "=f"(r) : "f"(x)); return r;
}
__device__ __forceinline__ float sigfast(float x) {
    return fmaf(tanhfast(0.5f * x), 0.5f, 0.5f);
}

// -------- persistent device scratch --------
__device__ float    g_xp[(size_t)T_STEPS * BATCH * G4];   // x_proj[t][b][g]
__device__ float    g_hT2[2][4 * 4096];                   // h: [buf][bg*4096 + k*8 + b]
__device__ unsigned g_bar4[4][32];                        // per-bg barrier counters (128B apart)

// ============================================================================
// Kernel A: x_proj = seq @ W_ih^T + (b_ih + b_hh)   (unchanged — control)
// ============================================================================
__global__ __launch_bounds__(256) void xproj_kernel(
    const float* __restrict__ seq,
    const float* __restrict__ Wih,
    const float* __restrict__ bih,
    const float* __restrict__ bhh)
{
    extern __shared__ float smA[];
    float* As = smA;            // 2 x 4096 floats: [k][m], m ^ (((k>>2)&7)<<2)
    float* Bs = smA + 8192;     // 2 x 2048 floats: [k][n], n ^ (((k>>2)&7)<<2)

    const int tid = threadIdx.x;
    const int m0g = blockIdx.y * 128;
    const int n0g = blockIdx.x * 64;
    const int tx  = tid & 15;
    const int ty  = tid >> 4;

    int baseA[4]; const float* gA[4];
    #pragma unroll
    for (int i = 0; i < 4; ++i) {
        int flat = tid + i * 256;
        int kq = flat & 7;
        int m  = flat >> 3;
        baseA[i] = (kq * 4) * 128 + (m ^ (kq << 2));
        gA[i] = seq + (size_t)(m0g + m) * 512 + kq * 4;
    }
    int baseB[2]; const float* gB[2];
    #pragma unroll
    for (int i = 0; i < 2; ++i) {
        int flat = tid + i * 256;
        int kq = flat & 7;
        int n  = flat >> 3;
        baseB[i] = (kq * 4) * 64 + (n ^ (kq << 2));
        gB[i] = Wih + (size_t)(n0g + n) * 512 + kq * 4;
    }

    u64 acc[4][4];
    #pragma unroll
    for (int i = 0; i < 4; ++i)
        #pragma unroll
        for (int j = 0; j < 4; ++j) acc[i][j] = 0ull;

    #pragma unroll
    for (int i = 0; i < 4; ++i) {
        float4 v = *(const float4*)(gA[i]);
        As[baseA[i]      ] = v.x;
        As[baseA[i] + 128] = v.y;
        As[baseA[i] + 256] = v.z;
        As[baseA[i] + 384] = v.w;
    }
    #pragma unroll
    for (int i = 0; i < 2; ++i) {
        float4 v = *(const float4*)(gB[i]);
        Bs[baseB[i]      ] = v.x;
        Bs[baseB[i] + 64 ] = v.y;
        Bs[baseB[i] + 128] = v.z;
        Bs[baseB[i] + 192] = v.w;
    }
    __syncthreads();

    for (int it = 0; it < 16; ++it) {
        const int p = it & 1;
        float4 a4[4], b4[2];
        if (it < 15) {
            const int kb = (it + 1) * 32;
            #pragma unroll
            for (int i = 0; i < 4; ++i) a4[i] = *(const float4*)(gA[i] + kb);
            #pragma unroll
            for (int i = 0; i < 2; ++i) b4[i] = *(const float4*)(gB[i] + kb);
        }

        const float* Ap = As + p * 4096;
        const float* Bp = Bs + p * 2048;
        #pragma unroll
        for (int kk = 0; kk < 32; ++kk) {
            const int c = ((kk >> 2) & 7) << 2;
            ulonglong2 A0 = *(const ulonglong2*)(Ap + kk * 128 + ((ty * 8    ) ^ c));
            ulonglong2 A1 = *(const ulonglong2*)(Ap + kk * 128 + ((ty * 8 + 4) ^ c));
            float4 bv     = *(const float4*)    (Bp + kk * 64  + ((tx * 4    ) ^ c));
            u64 b0 = pk2(bv.x), b1 = pk2(bv.y), b2 = pk2(bv.z), b3 = pk2(bv.w);
            ffma2(acc[0][0], A0.x, b0, acc[0][0]);
            ffma2(acc[0][1], A0.x, b1, acc[0][1]);
            ffma2(acc[0][2], A0.x, b2, acc[0][2]);
            ffma2(acc[0][3], A0.x, b3, acc[0][3]);
            ffma2(acc[1][0], A0.y, b0, acc[1][0]);
            ffma2(acc[1][1], A0.y, b1, acc[1][1]);
            ffma2(acc[1][2], A0.y, b2, acc[1][2]);
            ffma2(acc[1][3], A0.y, b3, acc[1][3]);
            ffma2(acc[2][0], A1.x, b0, acc[2][0]);
            ffma2(acc[2][1], A1.x, b1, acc[2][1]);
            ffma2(acc[2][2], A1.x, b2, acc[2][2]);
            ffma2(acc[2][3], A1.x, b3, acc[2][3]);
            ffma2(acc[3][0], A1.y, b0, acc[3][0]);
            ffma2(acc[3][1], A1.y, b1, acc[3][1]);
            ffma2(acc[3][2], A1.y, b2, acc[3][2]);
            ffma2(acc[3][3], A1.y, b3, acc[3][3]);
        }

        if (it < 15) {
            float* Aw = As + (p ^ 1) * 4096;
            float* Bw = Bs + (p ^ 1) * 2048;
            #pragma unroll
            for (int i = 0; i < 4; ++i) {
                Aw[baseA[i]      ] = a4[i].x;
                Aw[baseA[i] + 128] = a4[i].y;
                Aw[baseA[i] + 256] = a4[i].z;
                Aw[baseA[i] + 384] = a4[i].w;
            }
            #pragma unroll
            for (int i = 0; i < 2; ++i) {
                Bw[baseB[i]      ] = b4[i].x;
                Bw[baseB[i] + 64 ] = b4[i].y;
                Bw[baseB[i] + 128] = b4[i].z;
                Bw[baseB[i] + 192] = b4[i].w;
            }
        }
        __syncthreads();
    }

    float bs[4];
    #pragma unroll
    for (int j = 0; j < 4; ++j)
        bs[j] = bih[n0g + tx * 4 + j] + bhh[n0g + tx * 4 + j];

    #pragma unroll
    for (int mp = 0; mp < 4; ++mp) {
        float2 p0 = up2(acc[mp][0]);
        float2 p1 = up2(acc[mp][1]);
        float2 p2 = up2(acc[mp][2]);
        float2 p3 = up2(acc[mp][3]);
        float4 r0 = make_float4(p0.x + bs[0], p1.x + bs[1], p2.x + bs[2], p3.x + bs[3]);
        float4 r1 = make_float4(p0.y + bs[0], p1.y + bs[1], p2.y + bs[2], p3.y + bs[3]);
        size_t row0 = (size_t)(m0g + ty * 8 + 2 * mp) * 2048 + n0g + tx * 4;
        __stcs((float4*)(g_xp + row0), r0);
        __stcs((float4*)(g_xp + row0 + 2048), r1);
    }
}

// ============================================================================
// init: zero barrier counters, prefill g_hT2[0] with h0 (bg-major transpose)
// ============================================================================
__global__ void init_kernel(const float* __restrict__ h0) {
    int i = blockIdx.x * 256 + threadIdx.x;     // 64 CTAs x 256 = 16384
    if (i < 4 * 4096) {
        int bg = i >> 12, k = (i >> 3) & 511, b = i & 7;
        g_hT2[0][i] = h0[(bg * 8 + b) * 512 + k];
    }
    if (blockIdx.x == 0 && threadIdx.x < 4) g_bar4[threadIdx.x][0] = 0u;
}

// ============================================================================
// Kernel B: persistent recurrence, 256 CTAs (2/SM), 4 independent batch
//   domains. CTA (bg, jg): hidden slice jg*8..+8 (32 W rows), batch bg*8..+8.
//   Co-resident CTA pairs are from different domains -> latency phases of one
//   domain overlap with GEMM compute of the other.
//   GEMM: warp w owns k in [64w,64w+64); whole warp walks k together
//   (conflict-free SMEM, no swizzle). h staged pre-packed as f32x2 pairs.
// ============================================================================
__global__ __launch_bounds__(256, 2) void lstm_rec_kernel(
    const float* __restrict__ h0,
    const float* __restrict__ c0,
    const float* __restrict__ Whh,
    float* __restrict__ out,
    long long out_size)
{
    extern __shared__ float sm[];
    float* Ws  = sm;                     // 512*32 floats: [k][r], r = q*8+j   (64KB)
    u64*   Hs2 = (u64*)(Ws + 512 * 32);  // 4096 u64: [k*8+b] = {h,h} packed   (32KB)
    u64*   Red = Hs2 + 4096;             // 8 warps * 16 rpairs * 9            (9KB)

    const int tid  = threadIdx.x;
    const int wid  = tid >> 5;
    const int lane = tid & 31;
    const int ct   = blockIdx.x;
    const int bg   = ct >> 6;                  // batch domain [0,4)
    const int jg   = ct & 63;                  // j-group [0,64)
    const int jb   = jg * 8;
    const int bb   = bg * 8;

    // ---- one-time: W_hh rows -> K-major SMEM [k][r] (conflict-free STS) ----
    for (int idx = tid; idx < 32 * 512; idx += 256) {
        int r = idx & 31, k = idx >> 5;
        int q = r >> 3, j = r & 7;
        Ws[k * 32 + r] = Whh[(size_t)(q * 512 + jb + j) * 512 + k];
    }
    const int jj  = tid & 7;                   // cell j (tid<64)
    const int bbt = tid >> 3;                  // cell b (tid<64)
    float creg = 0.f;
    if (tid < 64) creg = c0[(bb + bbt) * 512 + jb + jj];
    __syncthreads();

    const int tm = lane & 7;                   // rows 4tm..4tm+3
    const int tn = lane >> 3;                  // b pair 2tn
    const float* wsp  = Ws + (wid * 64) * 32 + 4 * tm;
    const u64*   hsp  = Hs2 + (size_t)wid * 512 + 2 * tn;
    u64*         hstg = Hs2 + (size_t)wid * 512;

    unsigned* const barp = &g_bar4[bg][0];

    for (int t = 0; t < T_STEPS; ++t) {
        // xp prefetch (DRAM latency hidden behind GEMM)
        float xq0 = 0.f, xq1 = 0.f, xq2 = 0.f, xq3 = 0.f;
        if (tid < 64) {
            size_t base = ((size_t)t * 32 + bb + bbt) * 2048 + jb + jj;
            xq0 = __ldcs(&g_xp[base]);
            xq1 = __ldcs(&g_xp[base + 512]);
            xq2 = __ldcs(&g_xp[base + 1024]);
            xq3 = __ldcs(&g_xp[base + 1536]);
        }

        // ---- per-warp h staging: warp w stages k in [64w,64w+64), packed ----
        {
            const float* hsrc = g_hT2[t & 1] + bg * 4096 + wid * 512;
            #pragma unroll
            for (int i = 0; i < 4; ++i) {
                int f = i * 32 + lane;                // [0,128)
                float4 v = __ldcg((const float4*)(hsrc + f * 4));
                ulonglong2 p0 = make_ulonglong2(pk2(v.x), pk2(v.y));
                ulonglong2 p1 = make_ulonglong2(pk2(v.z), pk2(v.w));
                *(ulonglong2*)(hstg + f * 4    ) = p0;
                *(ulonglong2*)(hstg + f * 4 + 2) = p1;
            }
            __syncwarp();
        }

        // ---- warp GEMM: 4 rows x 2 b per thread over 64 k ----
        u64 a00 = 0ull, a01 = 0ull, a10 = 0ull, a11 = 0ull;
        #pragma unroll 16
        for (int kk = 0; kk < 64; ++kk) {
            ulonglong2 W2 = *(const ulonglong2*)(wsp + kk * 32);
            ulonglong2 H2 = *(const ulonglong2*)(hsp + kk * 8);
            ffma2(a00, W2.x, H2.x, a00);
            ffma2(a01, W2.x, H2.y, a01);
            ffma2(a10, W2.y, H2.x, a10);
            ffma2(a11, W2.y, H2.y, a11);
        }

        Red[(wid * 16 + 2 * tm    ) * 9 + 2 * tn    ] = a00;
        Red[(wid * 16 + 2 * tm    ) * 9 + 2 * tn + 1] = a01;
        Red[(wid * 16 + 2 * tm + 1) * 9 + 2 * tn    ] = a10;
        Red[(wid * 16 + 2 * tm + 1) * 9 + 2 * tn + 1] = a11;
        __syncthreads();

        // ---- merged reduce + cell: thread (j,b) reduces its 4 gate rows ----
        if (tid < 64) {
            const int j = jj, b = bbt;
            float z[4];
            #pragma unroll
            for (int q = 0; q < 4; ++q) {
                const int rp = q * 4 + (j >> 1);       // row (q*8+j) >> 1
                u64 s = Red[rp * 9 + b];
                #pragma unroll
                for (int g = 1; g < 8; ++g)
                    fadd2(s, s, Red[(g * 16 + rp) * 9 + b]);
                float2 f = up2(s);
                z[q] = (j & 1) ? f.y : f.x;
            }
            float zi = xq0 + z[0];
            float zf = xq1 + z[1];
            float zg = xq2 + z[2];
            float zo = xq3 + z[3];
            float ig = sigfast(zi);
            float fg = sigfast(zf);
            float gg = tanhfast(zg);
            float og = sigfast(zo);
            float cn = fg * creg + ig * gg;
            creg = cn;
            float hn = og * tanhfast(cn);

            g_hT2[(t + 1) & 1][bg * 4096 + (jb + j) * 8 + b] = hn;
            out[((size_t)t * 32 + bb + b) * 512 + jb + j] = hn;

            if (t == T_STEPS - 1) {
                long long need = (long long)T_STEPS * BATCH * HID + 2LL * BATCH * HID;
                if (out_size >= need) {
                    size_t ob = (size_t)T_STEPS * BATCH * HID;
                    out[ob + (bb + b) * 512 + jb + j]               = hn;  // h_f
                    out[ob + BATCH * HID + (bb + b) * 512 + jb + j] = cn;  // c_f
                }
            }
        }
        __syncthreads();     // Red reads done; h stores issued

        // ---- per-domain barrier: release-add arrival, acquire-load poll ----
        if (t < T_STEPS - 1) {
            if (tid == 0) {
                asm volatile("red.release.gpu.global.add.u32 [%0], %1;"
                             :: "l"(barp), "r"(1u) : "memory");
                const unsigned target = (unsigned)(t + 1) * 64u;
                unsigned v;
                do {
                    asm volatile("ld.acquire.gpu.global.u32 %0, [%1];"
                                 : "=r"(v) : "l"(barp) : "memory");
                } while (v < target);
            }
            __syncthreads();
        }
    }
}

// ============================================================================
extern "C" void kernel_launch(void* const* d_in, const int* in_sizes, int n_in,
                              void* d_out, int out_size)
{
    const float* seq = (const float*)d_in[0];
    const float* h0  = (const float*)d_in[1];
    const float* c0  = (const float*)d_in[2];
    const float* Wih = (const float*)d_in[3];
    const float* Whh = (const float*)d_in[4];
    const float* bih = (const float*)d_in[5];
    const float* bhh = (const float*)d_in[6];
    float* out = (float*)d_out;
    (void)in_sizes; (void)n_in;

    size_t smemA = (size_t)(2 * 4096 + 2 * 2048) * sizeof(float);   // 49152
    cudaFuncSetAttribute(xproj_kernel,
                         cudaFuncAttributeMaxDynamicSharedMemorySize, (int)smemA);
    dim3 gA(2048 / 64, (T_STEPS * BATCH) / 128);   // (32, 512)
    xproj_kernel<<<gA, 256, smemA>>>(seq, Wih, bih, bhh);

    init_kernel<<<64, 256>>>(h0);

    size_t smemB = (size_t)(512 * 32) * sizeof(float)        // Ws   64KB
                 + (size_t)4096 * sizeof(u64)                // Hs2  32KB
                 + (size_t)(8 * 16 * 9) * sizeof(u64);       // Red   9KB
    cudaFuncSetAttribute(lstm_rec_kernel,
                         cudaFuncAttributeMaxDynamicSharedMemorySize, (int)smemB);
    lstm_rec_kernel<<<256, 256, smemB>>>(h0, c0, Whh, out, (long long)out_size);
}

// round 10
// speedup vs baseline: 1.2299x; 1.2299x over previous
#include <cuda_runtime.h>
#include <cuda_bf16.h>
#include <cstdint>

#define T_STEPS 2048
#define BATCH   32
#define INDIM   512
#define HID     512
#define G4      2048   // 4*HID

typedef unsigned long long u64;

// packed f32x2 helpers (sm_103a packed fp32 pipe)
__device__ __forceinline__ u64 pk2(float x) {
    u64 r; asm("mov.b64 %0, {%1, %1};" : "=l"(r) : "f"(x)); return r;
}
__device__ __forceinline__ void ffma2(u64& d, u64 a, u64 b, u64 c) {
    asm("fma.rn.f32x2 %0, %1, %2, %3;" : "=l"(d) : "l"(a), "l"(b), "l"(c));
}
__device__ __forceinline__ void fadd2(u64& d, u64 a, u64 b) {
    asm("add.rn.f32x2 %0, %1, %2;" : "=l"(d) : "l"(a), "l"(b));
}
__device__ __forceinline__ float2 up2(u64 v) {
    float2 f; asm("mov.b64 {%0, %1}, %2;" : "=f"(f.x), "=f"(f.y) : "l"(v)); return f;
}
__device__ __forceinline__ float tanhfast(float x) {
    float r; asm("tanh.approx.f32 %0, %1;" : "=f"(r) : "f"(x)); return r;
}
__device__ __forceinline__ float sigfast(float x) {
    return fmaf(tanhfast(0.5f * x), 0.5f, 0.5f);
}

// bf16 mma m16n8k16 (row.col), fp32 accumulate
__device__ __forceinline__ void mma_bf16(float* c,
    uint32_t a0, uint32_t a1, uint32_t a2, uint32_t a3,
    uint32_t b0, uint32_t b1)
{
    asm volatile(
        "mma.sync.aligned.m16n8k16.row.col.f32.bf16.bf16.f32 "
        "{%0,%1,%2,%3},{%4,%5,%6,%7},{%8,%9},{%0,%1,%2,%3};"
        : "+f"(c[0]), "+f"(c[1]), "+f"(c[2]), "+f"(c[3])
        : "r"(a0), "r"(a1), "r"(a2), "r"(a3), "r"(b0), "r"(b1));
}

__device__ __forceinline__ uint32_t packbf(__nv_bfloat16 a, __nv_bfloat16 b) {
    __nv_bfloat162 p = __halves2bfloat162(a, b);
    return *reinterpret_cast<uint32_t*>(&p);
}

// logical k-pair word w (0..15) -> physical word position within 16-word row
__device__ __forceinline__ int phiw(int w) {
    return (w & 8) | ((w & 3) << 1) | ((w >> 2) & 1);
}

// -------- persistent device scratch --------
__device__ float    g_xp[(size_t)T_STEPS * BATCH * G4];   // x_proj[t][b][g]
__device__ float    g_hT[2][HID * BATCH];                 // h transposed: [k][b]
__device__ unsigned g_bar2[2][32];                        // per-batch-group counters

// ============================================================================
// Kernel A (tensor): x_proj = seq @ W_ih^T + (b_ih + b_hh)
//   bf16 3-split (hi*hi + hi*lo + lo*hi), fp32 accum. 128x64x32 tiles,
//   8 warps each m32 x n32. SMEM rows: 16 k-pair words, pair-permuted +
//   XOR-swizzled for conflict-free LDS.64 fragment loads.
// ============================================================================
__global__ __launch_bounds__(256) void xproj_tc_kernel(
    const float* __restrict__ seq,
    const float* __restrict__ Wih,
    const float* __restrict__ bih,
    const float* __restrict__ bhh)
{
    __shared__ uint32_t Ah[128 * 16];
    __shared__ uint32_t Al[128 * 16];
    __shared__ uint32_t Bh[64 * 16];
    __shared__ uint32_t Bl[64 * 16];

    const int tid  = threadIdx.x;
    const int lane = tid & 31;
    const int warp = tid >> 5;
    const int m0g  = blockIdx.y * 128;
    const int n0g  = blockIdx.x * 64;
    const int m0w  = (warp >> 1) * 32;
    const int n0w  = (warp & 1) * 32;
    const int q    = lane & 3;
    const int qr   = lane >> 2;

    float acc[2][4][4];
    #pragma unroll
    for (int i = 0; i < 2; ++i)
        #pragma unroll
        for (int j = 0; j < 4; ++j)
            #pragma unroll
            for (int v = 0; v < 4; ++v) acc[i][j][v] = 0.f;

    for (int kb = 0; kb < 512; kb += 32) {
        // ---- load + split-convert A tile (128 x 32) ----
        #pragma unroll
        for (int i = 0; i < 4; ++i) {
            int flat = tid + i * 256;            // [0,1024)
            int kq = flat & 7;
            int m  = flat >> 3;
            float4 v = *(const float4*)(seq + (size_t)(m0g + m) * 512 + kb + kq * 4);
            __nv_bfloat16 hx = __float2bfloat16_rn(v.x);
            __nv_bfloat16 hy = __float2bfloat16_rn(v.y);
            __nv_bfloat16 hz = __float2bfloat16_rn(v.z);
            __nv_bfloat16 hw = __float2bfloat16_rn(v.w);
            __nv_bfloat16 lx = __float2bfloat16_rn(v.x - __bfloat162float(hx));
            __nv_bfloat16 ly = __float2bfloat16_rn(v.y - __bfloat162float(hy));
            __nv_bfloat16 lz = __float2bfloat16_rn(v.z - __bfloat162float(hz));
            __nv_bfloat16 lw = __float2bfloat16_rn(v.w - __bfloat162float(hw));
            int sw = ((m >> 1) & 1) << 3;
            int p0 = m * 16 + (phiw(2 * kq    ) ^ sw);
            int p1 = m * 16 + (phiw(2 * kq + 1) ^ sw);
            Ah[p0] = packbf(hx, hy);  Al[p0] = packbf(lx, ly);
            Ah[p1] = packbf(hz, hw);  Al[p1] = packbf(lz, lw);
        }
        // ---- load + split-convert B tile (64 x 32) ----
        #pragma unroll
        for (int i = 0; i < 2; ++i) {
            int flat = tid + i * 256;            // [0,512)
            int kq = flat & 7;
            int n  = flat >> 3;
            float4 v = *(const float4*)(Wih + (size_t)(n0g + n) * 512 + kb + kq * 4);
            __nv_bfloat16 hx = __float2bfloat16_rn(v.x);
            __nv_bfloat16 hy = __float2bfloat16_rn(v.y);
            __nv_bfloat16 hz = __float2bfloat16_rn(v.z);
            __nv_bfloat16 hw = __float2bfloat16_rn(v.w);
            __nv_bfloat16 lx = __float2bfloat16_rn(v.x - __bfloat162float(hx));
            __nv_bfloat16 ly = __float2bfloat16_rn(v.y - __bfloat162float(hy));
            __nv_bfloat16 lz = __float2bfloat16_rn(v.z - __bfloat162float(hz));
            __nv_bfloat16 lw = __float2bfloat16_rn(v.w - __bfloat162float(hw));
            int sw = ((n >> 1) & 1) << 3;
            int p0 = n * 16 + (phiw(2 * kq    ) ^ sw);
            int p1 = n * 16 + (phiw(2 * kq + 1) ^ sw);
            Bh[p0] = packbf(hx, hy);  Bl[p0] = packbf(lx, ly);
            Bh[p1] = packbf(hz, hw);  Bl[p1] = packbf(lz, lw);
        }
        __syncthreads();

        #pragma unroll
        for (int kt = 0; kt < 2; ++kt) {
            const int offBase = (kt << 3) | (q << 1);
            // A fragments for tm = 0,1 (hi and lo)
            uint32_t ah[2][4], al[2][4];
            #pragma unroll
            for (int tm = 0; tm < 2; ++tm) {
                int r   = m0w + tm * 16 + qr;
                int off = offBase ^ (((r >> 1) & 1) << 3);   // same for r and r+8
                u64 t0 = *(const u64*)(Ah + r * 16 + off);
                u64 t1 = *(const u64*)(Ah + (r + 8) * 16 + off);
                ah[tm][0] = (uint32_t)t0; ah[tm][2] = (uint32_t)(t0 >> 32);
                ah[tm][1] = (uint32_t)t1; ah[tm][3] = (uint32_t)(t1 >> 32);
                u64 s0 = *(const u64*)(Al + r * 16 + off);
                u64 s1 = *(const u64*)(Al + (r + 8) * 16 + off);
                al[tm][0] = (uint32_t)s0; al[tm][2] = (uint32_t)(s0 >> 32);
                al[tm][1] = (uint32_t)s1; al[tm][3] = (uint32_t)(s1 >> 32);
            }
            #pragma unroll
            for (int tn = 0; tn < 4; ++tn) {
                int rn   = n0w + tn * 8 + qr;
                int offb = offBase ^ (((rn >> 1) & 1) << 3);
                u64 hb = *(const u64*)(Bh + rn * 16 + offb);
                u64 lb = *(const u64*)(Bl + rn * 16 + offb);
                uint32_t bh0 = (uint32_t)hb, bh1 = (uint32_t)(hb >> 32);
                uint32_t bl0 = (uint32_t)lb, bl1 = (uint32_t)(lb >> 32);
                #pragma unroll
                for (int tm = 0; tm < 2; ++tm) {
                    mma_bf16(acc[tm][tn], ah[tm][0], ah[tm][1], ah[tm][2], ah[tm][3], bh0, bh1);
                    mma_bf16(acc[tm][tn], ah[tm][0], ah[tm][1], ah[tm][2], ah[tm][3], bl0, bl1);
                    mma_bf16(acc[tm][tn], al[tm][0], al[tm][1], al[tm][2], al[tm][3], bh0, bh1);
                }
            }
        }
        __syncthreads();
    }

    // ---- epilogue: add bias, store fp32 ----
    #pragma unroll
    for (int tn = 0; tn < 4; ++tn) {
        int c0 = n0g + n0w + tn * 8 + q * 2;
        float b0 = bih[c0]     + bhh[c0];
        float b1 = bih[c0 + 1] + bhh[c0 + 1];
        #pragma unroll
        for (int tm = 0; tm < 2; ++tm) {
            int row = m0g + m0w + tm * 16 + qr;
            float2 v0 = make_float2(acc[tm][tn][0] + b0, acc[tm][tn][1] + b1);
            float2 v1 = make_float2(acc[tm][tn][2] + b0, acc[tm][tn][3] + b1);
            __stcs((float2*)(g_xp + (size_t)row * 2048 + c0), v0);
            __stcs((float2*)(g_xp + (size_t)(row + 8) * 2048 + c0), v1);
        }
    }
}

// ============================================================================
__global__ void reset_kernel() {
    if (threadIdx.x < 2) g_bar2[threadIdx.x][0] = 0u;
}

// ============================================================================
// Kernel B: persistent recurrence — EXACT R4 structure (best measured).
// ============================================================================
__global__ __launch_bounds__(256) void lstm_rec_kernel(
    const float* __restrict__ h0,
    const float* __restrict__ c0,
    const float* __restrict__ Whh,
    float* __restrict__ out,
    long long out_size)
{
    extern __shared__ float sm[];
    float* Ws  = sm;                           // 512*32: [k][r], r^(((k>>5)&1)<<2)
    float* Hs  = Ws + 512 * 32;                // 512*32: [k][b], b^(((k>>5)&1)<<4)
    u64*   Red = (u64*)(Hs + 512 * 32);        // 16 groups * 16 r-pairs * 17
    float* Gs  = (float*)(Red + 16 * 16 * 17); // 512
    float* Cs  = Gs + 512;                     // 128

    const int tid = threadIdx.x;
    const int ct  = blockIdx.x;
    const int jg  = ct >> 1;
    const int bg  = ct & 1;
    const int jb  = jg * 8;
    const int bb  = bg * 16;

    for (int idx = tid; idx < 32 * 512; idx += 256) {
        int r = idx & 31, k = idx >> 5;
        int q = r >> 3, j = r & 7;
        float w = Whh[(size_t)(q * 512 + jb + j) * 512 + k];
        Ws[k * 32 + (r ^ (((k >> 5) & 1) << 2))] = w;
    }
    const int jj  = tid & 7;
    const int bbt = tid >> 3;
    if (tid < 128) Cs[bbt * 8 + jj] = c0[(bb + bbt) * 512 + jb + jj];
    for (int idx = tid; idx < 512 * 16; idx += 256) {
        int b = idx & 15, k = idx >> 4;
        Hs[k * 32 + (b ^ (((k >> 5) & 1) << 4))] = h0[(bb + b) * 512 + k];
    }
    __syncthreads();

    const int gid = tid >> 4;
    const int l16 = tid & 15;
    const int tm  = l16 & 3;
    const int tn  = l16 >> 2;
    const int cA  = (gid & 1) << 2;
    const int cH  = (gid & 1) << 4;
    const float* wsp = Ws + (size_t)gid * 32 * 32;
    const float* hsp = Hs + (size_t)gid * 32 * 32;
    const int aw0 = (tm * 8    ) ^ cA;
    const int aw1 = (tm * 8 + 4) ^ cA;
    const int hw  = (tn * 4    ) ^ cH;

    for (int t = 0; t < T_STEPS; ++t) {
        float xq0 = 0.f, xq1 = 0.f, xq2 = 0.f, xq3 = 0.f;
        if (tid < 128) {
            size_t base = ((size_t)t * 32 + bb + bbt) * 2048 + jb + jj;
            xq0 = __ldcs(&g_xp[base]);
            xq1 = __ldcs(&g_xp[base + 512]);
            xq2 = __ldcs(&g_xp[base + 1024]);
            xq3 = __ldcs(&g_xp[base + 1536]);
        }

        if (t > 0) {
            const float* hsrc = g_hT[t & 1];
            #pragma unroll
            for (int i = 0; i < 8; ++i) {
                int flat = tid + i * 256;
                int q  = flat & 3;
                int kr = flat >> 2;
                float4 v = __ldcg((const float4*)(hsrc + kr * 32 + bb + q * 4));
                *(float4*)(Hs + kr * 32 + ((q * 4) ^ (((kr >> 5) & 1) << 4))) = v;
            }
            __syncthreads();
        }

        u64 acc[4][4];
        #pragma unroll
        for (int i = 0; i < 4; ++i)
            #pragma unroll
            for (int j = 0; j < 4; ++j) acc[i][j] = 0ull;

        #pragma unroll 8
        for (int k = 0; k < 32; ++k) {
            ulonglong2 A0 = *(const ulonglong2*)(wsp + k * 32 + aw0);
            ulonglong2 A1 = *(const ulonglong2*)(wsp + k * 32 + aw1);
            float4 bv     = *(const float4*)    (hsp + k * 32 + hw);
            u64 b0 = pk2(bv.x), b1 = pk2(bv.y), b2 = pk2(bv.z), b3 = pk2(bv.w);
            ffma2(acc[0][0], A0.x, b0, acc[0][0]);
            ffma2(acc[0][1], A0.x, b1, acc[0][1]);
            ffma2(acc[0][2], A0.x, b2, acc[0][2]);
            ffma2(acc[0][3], A0.x, b3, acc[0][3]);
            ffma2(acc[1][0], A0.y, b0, acc[1][0]);
            ffma2(acc[1][1], A0.y, b1, acc[1][1]);
            ffma2(acc[1][2], A0.y, b2, acc[1][2]);
            ffma2(acc[1][3], A0.y, b3, acc[1][3]);
            ffma2(acc[2][0], A1.x, b0, acc[2][0]);
            ffma2(acc[2][1], A1.x, b1, acc[2][1]);
            ffma2(acc[2][2], A1.x, b2, acc[2][2]);
            ffma2(acc[2][3], A1.x, b3, acc[2][3]);
            ffma2(acc[3][0], A1.y, b0, acc[3][0]);
            ffma2(acc[3][1], A1.y, b1, acc[3][1]);
            ffma2(acc[3][2], A1.y, b2, acc[3][2]);
            ffma2(acc[3][3], A1.y, b3, acc[3][3]);
        }

        #pragma unroll
        for (int mp = 0; mp < 4; ++mp)
            #pragma unroll
            for (int n = 0; n < 4; ++n)
                Red[(gid * 16 + tm * 4 + mp) * 17 + (tn * 4 + n)] = acc[mp][n];
        __syncthreads();

        {
            int rp = tid >> 4, b = tid & 15;
            u64 s = Red[rp * 17 + b];
            #pragma unroll
            for (int g = 1; g < 16; ++g)
                fadd2(s, s, Red[(g * 16 + rp) * 17 + b]);
            float2 f = up2(s);
            Gs[(rp * 2    ) * 16 + b] = f.x;
            Gs[(rp * 2 + 1) * 16 + b] = f.y;
        }
        __syncthreads();

        if (tid < 128) {
            const int j = jj, b = bbt;
            float zi = xq0 + Gs[(     j) * 16 + b];
            float zf = xq1 + Gs[( 8 + j) * 16 + b];
            float zg = xq2 + Gs[(16 + j) * 16 + b];
            float zo = xq3 + Gs[(24 + j) * 16 + b];
            float ig = sigfast(zi);
            float fg = sigfast(zf);
            float gg = tanhfast(zg);
            float og = sigfast(zo);
            float cn = fg * Cs[b * 8 + j] + ig * gg;
            Cs[b * 8 + j] = cn;
            float hn = og * tanhfast(cn);

            g_hT[(t + 1) & 1][(jb + j) * 32 + bb + b] = hn;
            out[((size_t)t * 32 + bb + b) * 512 + jb + j] = hn;

            if (t == T_STEPS - 1) {
                long long need = (long long)T_STEPS * BATCH * HID + 2LL * BATCH * HID;
                if (out_size >= need) {
                    size_t ob = (size_t)T_STEPS * BATCH * HID;
                    out[ob + (bb + b) * 512 + jb + j]               = hn;
                    out[ob + BATCH * HID + (bb + b) * 512 + jb + j] = cn;
                }
            }
        }

        if (t < T_STEPS - 1) {
            __threadfence();
            __syncthreads();
            if (tid == 0) {
                atomicAdd(&g_bar2[bg][0], 1u);
                unsigned target = (unsigned)(t + 1) * 64u;
                while (*((volatile unsigned*)&g_bar2[bg][0]) < target) { }
            }
            __syncthreads();
        }
    }
}

// ============================================================================
extern "C" void kernel_launch(void* const* d_in, const int* in_sizes, int n_in,
                              void* d_out, int out_size)
{
    const float* seq = (const float*)d_in[0];
    const float* h0  = (const float*)d_in[1];
    const float* c0  = (const float*)d_in[2];
    const float* Wih = (const float*)d_in[3];
    const float* Whh = (const float*)d_in[4];
    const float* bih = (const float*)d_in[5];
    const float* bhh = (const float*)d_in[6];
    float* out = (float*)d_out;
    (void)in_sizes; (void)n_in;

    dim3 gA(2048 / 64, (T_STEPS * BATCH) / 128);   // (32, 512)
    xproj_tc_kernel<<<gA, 256>>>(seq, Wih, bih, bhh);

    reset_kernel<<<1, 32>>>();

    size_t smem = (size_t)(512 * 32 + 512 * 32 + 512) * sizeof(float)
                + (size_t)(16 * 16 * 17) * sizeof(u64)
                + (size_t)128 * sizeof(float);
    cudaFuncSetAttribute(lstm_rec_kernel,
                         cudaFuncAttributeMaxDynamicSharedMemorySize, (int)smem);
    lstm_rec_kernel<<<128, 256, smem>>>(h0, c0, Whh, out, (long long)out_size);
}